// round 9
// baseline (speedup 1.0000x reference)
#include <cuda_runtime.h>
#include <math.h>

#define BB 64
#define NN 128
#define DD 512
#define D3 1536

// ---------------- scratch (device globals; no allocation) ----------------
__device__ float g_gi[BB * NN * D3];      // x @ Wi_c^T + bi_c   (50.3 MB)
__device__ float g_gh[BB * NN * D3];      // x @ Wh_p^T + bh_p   (50.3 MB)
__device__ float g_qb[BB * NN];           // x . wq + lin_b
__device__ float g_hk[BB * NN];           // H[b,n] . wk (incremental)
__device__ float g_u[BB * 2 * DD];        // [u0 | u1] weighted sums (64 x 1024)
__device__ float g_Mpart[4 * BB * DD];    // split-K partials of M (64 x 512)
__device__ float g_Gpart[2 * BB * 3072];  // split-K partials of gates (64 x 3072)

__device__ __forceinline__ float gru_out(float ir, float iz, float inn,
                                         float hr, float hz, float hn, float h) {
    float r = 1.f / (1.f + expf(-(ir + hr)));
    float z = 1.f / (1.f + expf(-(iz + hz)));
    float n = tanhf(inn + r * hn);
    return (1.f - z) * n + z * h;
}

// ---------------- precompute GEMM: C[m,n] = sum_k A[m,k]*W[n,k] + bias[n] ----
// 128x128 tile, BK=8, 256 threads, 8x8 microtile. dst: 0 -> g_gi, 1 -> g_gh.
__global__ __launch_bounds__(256) void gemm_nt_bias(
    const float* __restrict__ A, const float* __restrict__ W,
    const float* __restrict__ bias, int dst,
    int lda, int ldw, int ldc, int K)
{
    __shared__ __align__(16) float As[8][128];
    __shared__ __align__(16) float Ws[8][128];
    float* C = dst ? g_gh : g_gi;
    int t = threadIdx.x;
    int m0 = blockIdx.y * 128;
    int n0 = blockIdx.x * 128;
    int ar = t >> 1, ak = (t & 1) * 4;
    int ty = t >> 4, tx = t & 15;
    float acc[8][8];
#pragma unroll
    for (int i = 0; i < 8; i++)
#pragma unroll
        for (int j = 0; j < 8; j++) acc[i][j] = 0.f;

    for (int k0 = 0; k0 < K; k0 += 8) {
        float4 av = *(const float4*)(A + (size_t)(m0 + ar) * lda + k0 + ak);
        float4 wv = *(const float4*)(W + (size_t)(n0 + ar) * ldw + k0 + ak);
        As[ak + 0][ar] = av.x; As[ak + 1][ar] = av.y;
        As[ak + 2][ar] = av.z; As[ak + 3][ar] = av.w;
        Ws[ak + 0][ar] = wv.x; Ws[ak + 1][ar] = wv.y;
        Ws[ak + 2][ar] = wv.z; Ws[ak + 3][ar] = wv.w;
        __syncthreads();
#pragma unroll
        for (int k = 0; k < 8; k++) {
            float a[8], w[8];
            *(float4*)&a[0] = *(const float4*)&As[k][ty * 8];
            *(float4*)&a[4] = *(const float4*)&As[k][ty * 8 + 4];
            *(float4*)&w[0] = *(const float4*)&Ws[k][tx * 8];
            *(float4*)&w[4] = *(const float4*)&Ws[k][tx * 8 + 4];
#pragma unroll
            for (int i = 0; i < 8; i++)
#pragma unroll
                for (int j = 0; j < 8; j++) acc[i][j] += a[i] * w[j];
        }
        __syncthreads();
    }
#pragma unroll
    for (int i = 0; i < 8; i++) {
        int m = m0 + ty * 8 + i;
#pragma unroll
        for (int j = 0; j < 8; j++) {
            int n = n0 + tx * 8 + j;
            C[(size_t)m * ldc + n] = acc[i][j] + bias[n];
        }
    }
}

// ---------------- qb: g_qb[row] = features[row,:] . wq + lin_b -------------
__global__ __launch_bounds__(128) void qb_kernel(
    const float* __restrict__ feat, const float* __restrict__ lin_w,
    const float* __restrict__ lin_b)
{
    __shared__ float sred[128];
    int row = blockIdx.x;
    int t = threadIdx.x;
    const float* x = feat + (size_t)row * DD;
    float s = x[t] * lin_w[t] + x[t + 128] * lin_w[t + 128]
            + x[t + 256] * lin_w[t + 256] + x[t + 384] * lin_w[t + 384];
    sred[t] = s;
    __syncthreads();
    for (int st = 64; st > 0; st >>= 1) {
        if (t < st) sred[t] += sred[t + st];
        __syncthreads();
    }
    if (t == 0) g_qb[row] = sred[0] + lin_b[0];
}

// ---------------- init: H[:,0] = C0 + P0, hk[:,0] --------------------------
__global__ __launch_bounds__(512) void init_kernel(
    const float* __restrict__ feat, const float* __restrict__ bh_c,
    const float* __restrict__ bi_p, const float* __restrict__ lin_w,
    float* __restrict__ H)
{
    __shared__ float sred[512];
    int b = blockIdx.x, d = threadIdx.x;
    const float* gi = g_gi + (size_t)(b * NN) * D3;   // row (b,0)
    const float* gh = g_gh + (size_t)(b * NN) * D3;
    // C0 = gru(x0, h=0; c):  gh_c = bh_c, final h-term = 0
    float C = gru_out(gi[d], gi[512 + d], gi[1024 + d],
                      bh_c[d], bh_c[512 + d], bh_c[1024 + d], 0.f);
    // P0 = gru(x=0, h=x0; p): gi_p = bi_p, gh_p precomputed, h-term = x0
    float x0 = feat[(size_t)(b * NN) * DD + d];
    float P = gru_out(bi_p[d], bi_p[512 + d], bi_p[1024 + d],
                      gh[d], gh[512 + d], gh[1024 + d], x0);
    float Hv = C + P;
    H[(size_t)(b * NN) * DD + d] = Hv;
    sred[d] = Hv * lin_w[512 + d];   // wk = lin_w[512:1024]
    __syncthreads();
    for (int st = 256; st > 0; st >>= 1) {
        if (d < st) sred[d] += sred[d + st];
        __syncthreads();
    }
    if (d == 0) g_hk[b * NN] = sred[0];
}

// ---------------- attention: softmax + weighted H sums ---------------------
__global__ __launch_bounds__(256) void attn_kernel(
    int i, const int* __restrict__ adj, const int* __restrict__ smask,
    const int* __restrict__ omask, const float* __restrict__ H)
{
    __shared__ float sa[128], sr[128], sw[128], sws[128], swo[128];
    int b = blockIdx.x, t = threadIdx.x;
    float a = -1e30f;
    int valid = 0, sm = 0, om = 0;
    if (t < NN) {
        valid = (t < i) && adj[(size_t)(b * NN + i) * NN + t];
        if (valid) {
            a = g_qb[b * NN + i] + g_hk[b * NN + t];
            sm = smask[(size_t)(b * NN + i) * NN + t];
            om = omask[(size_t)(b * NN + i) * NN + t];
        }
        sa[t] = a;
        sr[t] = a;
    }
    __syncthreads();
    for (int st = 64; st > 0; st >>= 1) {
        if (t < st) sr[t] = fmaxf(sr[t], sr[t + st]);
        __syncthreads();
    }
    float mx = sr[0];
    __syncthreads();
    float e = 0.f;
    if (t < NN) {
        e = valid ? expf(sa[t] - mx) : 0.f;
        sr[t] = e;
    }
    __syncthreads();
    for (int st = 64; st > 0; st >>= 1) {
        if (t < st) sr[t] += sr[t + st];
        __syncthreads();
    }
    float inv = 1.f / sr[0];
    if (t < NN) {
        float w = e * inv;
        sw[t] = w;
        sws[t] = w * (float)sm;
        swo[t] = w * (float)om;
    }
    __syncthreads();

    // u0 = sum_n w*s*H[b,n,:] ; u1 = sum_n w*o*H[b,n,:]  (d = t and t+256)
    float u0a = 0.f, u0b = 0.f, u1a = 0.f, u1b = 0.f;
    const float* Hb = H + (size_t)b * NN * DD;
    for (int n = 0; n < i; n++) {
        float w = sw[n];
        if (w == 0.f) continue;
        float ws = sws[n], wo = swo[n];
        float h0 = Hb[(size_t)n * DD + t];
        float h1 = Hb[(size_t)n * DD + t + 256];
        u0a += ws * h0; u0b += ws * h1;
        u1a += wo * h0; u1b += wo * h1;
    }
    float* ub = g_u + b * 1024;
    ub[t] = u0a; ub[t + 256] = u0b;
    ub[512 + t] = u1a; ub[768 + t] = u1b;
}

// ---------------- step GEMM 1: Mpart[kseg] = u @ [Wr0|Wr1]^T (split-K) ------
// grid (8, 4): x = 64-wide d tile, y = K segment (256 each over K=1024).
__global__ __launch_bounds__(256) void step_gemm_M(
    const float* __restrict__ Wr0, const float* __restrict__ Wr1)
{
    __shared__ __align__(16) float Us[16][64];
    __shared__ __align__(16) float Ws[16][64];
    int t = threadIdx.x;
    int dt0 = blockIdx.x * 64;
    int kseg = blockIdx.y;
    const float* Wb = (kseg < 2 ? Wr0 : Wr1) + (kseg & 1) * 256;
    const float* Ub = g_u + kseg * 256;
    int lr = t >> 2, lc = (t & 3) * 4;
    int ty = t >> 4, tx = t & 15;
    float acc[4][4];
#pragma unroll
    for (int i = 0; i < 4; i++)
#pragma unroll
        for (int j = 0; j < 4; j++) acc[i][j] = 0.f;

    for (int kk = 0; kk < 256; kk += 16) {
        float4 uv = *(const float4*)(Ub + lr * 1024 + kk + lc);
        float4 wv = *(const float4*)(Wb + (dt0 + lr) * 512 + kk + lc);
        Us[lc + 0][lr] = uv.x; Us[lc + 1][lr] = uv.y;
        Us[lc + 2][lr] = uv.z; Us[lc + 3][lr] = uv.w;
        Ws[lc + 0][lr] = wv.x; Ws[lc + 1][lr] = wv.y;
        Ws[lc + 2][lr] = wv.z; Ws[lc + 3][lr] = wv.w;
        __syncthreads();
#pragma unroll
        for (int k = 0; k < 16; k++) {
            float a[4], w[4];
            *(float4*)a = *(const float4*)&Us[k][ty * 4];
            *(float4*)w = *(const float4*)&Ws[k][tx * 4];
#pragma unroll
            for (int i = 0; i < 4; i++)
#pragma unroll
                for (int j = 0; j < 4; j++) acc[i][j] += a[i] * w[j];
        }
        __syncthreads();
    }
#pragma unroll
    for (int i = 0; i < 4; i++)
#pragma unroll
        for (int j = 0; j < 4; j++)
            g_Mpart[(kseg * 64 + ty * 4 + i) * 512 + dt0 + tx * 4 + j] = acc[i][j];
}

// ---------------- step GEMM 2: Gpart[kseg] = M @ [Wh_c;Wi_p]^T (split-K) ----
// grid (48, 2): x = 64-wide col tile over 3072, y = K segment (256 over K=512).
__global__ __launch_bounds__(256) void step_gemm_G(
    const float* __restrict__ Whc, const float* __restrict__ Wip)
{
    __shared__ __align__(16) float Ms[16][64];
    __shared__ __align__(16) float Ws[16][64];
    int t = threadIdx.x;
    int j0 = blockIdx.x * 64;
    int k0 = blockIdx.y * 256;
    const float* Wb = (j0 < 1536) ? (Whc + (size_t)j0 * 512)
                                  : (Wip + (size_t)(j0 - 1536) * 512);
    int lr = t >> 2, lc = (t & 3) * 4;
    int ty = t >> 4, tx = t & 15;
    float acc[4][4];
#pragma unroll
    for (int i = 0; i < 4; i++)
#pragma unroll
        for (int j = 0; j < 4; j++) acc[i][j] = 0.f;

    for (int kk = 0; kk < 256; kk += 16) {
        int k = k0 + kk + lc;
        float4 m0 = *(const float4*)(g_Mpart + (0 * 64 + lr) * 512 + k);
        float4 m1 = *(const float4*)(g_Mpart + (1 * 64 + lr) * 512 + k);
        float4 m2 = *(const float4*)(g_Mpart + (2 * 64 + lr) * 512 + k);
        float4 m3 = *(const float4*)(g_Mpart + (3 * 64 + lr) * 512 + k);
        float4 wv = *(const float4*)(Wb + lr * 512 + k);
        Ms[lc + 0][lr] = m0.x + m1.x + m2.x + m3.x;
        Ms[lc + 1][lr] = m0.y + m1.y + m2.y + m3.y;
        Ms[lc + 2][lr] = m0.z + m1.z + m2.z + m3.z;
        Ms[lc + 3][lr] = m0.w + m1.w + m2.w + m3.w;
        Ws[lc + 0][lr] = wv.x; Ws[lc + 1][lr] = wv.y;
        Ws[lc + 2][lr] = wv.z; Ws[lc + 3][lr] = wv.w;
        __syncthreads();
#pragma unroll
        for (int k2 = 0; k2 < 16; k2++) {
            float a[4], w[4];
            *(float4*)a = *(const float4*)&Ms[k2][ty * 4];
            *(float4*)w = *(const float4*)&Ws[k2][tx * 4];
#pragma unroll
            for (int i = 0; i < 4; i++)
#pragma unroll
                for (int j = 0; j < 4; j++) acc[i][j] += a[i] * w[j];
        }
        __syncthreads();
    }
#pragma unroll
    for (int i = 0; i < 4; i++)
#pragma unroll
        for (int j = 0; j < 4; j++)
            g_Gpart[(size_t)(blockIdx.y * 64 + ty * 4 + i) * 3072 + j0 + tx * 4 + j]
                = acc[i][j];
}

// ---------------- GRU fuse: H[:,i] = C + P, hk[:,i] -------------------------
__global__ __launch_bounds__(512) void gru_kernel(
    int i, const float* __restrict__ feat, const float* __restrict__ bh_c,
    const float* __restrict__ bi_p, const float* __restrict__ lin_w,
    float* __restrict__ H)
{
    __shared__ float sred[512];
    int b = blockIdx.x, d = threadIdx.x;
    float Mv = g_Mpart[(0 * 64 + b) * 512 + d] + g_Mpart[(1 * 64 + b) * 512 + d]
             + g_Mpart[(2 * 64 + b) * 512 + d] + g_Mpart[(3 * 64 + b) * 512 + d];
    const float* gi = g_gi + (size_t)(b * NN + i) * D3;
    const float* gh = g_gh + (size_t)(b * NN + i) * D3;
    const float* G0 = g_Gpart + (size_t)b * 3072;
    const float* G1 = g_Gpart + (size_t)(64 + b) * 3072;
    // C = gru(x, M; c): gi precomputed (incl bi_c), gh = M@Wh_c^T + bh_c
    float hr = G0[d] + G1[d] + bh_c[d];
    float hz = G0[512 + d] + G1[512 + d] + bh_c[512 + d];
    float hn = G0[1024 + d] + G1[1024 + d] + bh_c[1024 + d];
    float C = gru_out(gi[d], gi[512 + d], gi[1024 + d], hr, hz, hn, Mv);
    // P = gru(M, x; p): gi = M@Wi_p^T + bi_p, gh precomputed (incl bh_p)
    float pir = G0[1536 + d] + G1[1536 + d] + bi_p[d];
    float piz = G0[2048 + d] + G1[2048 + d] + bi_p[512 + d];
    float pin = G0[2560 + d] + G1[2560 + d] + bi_p[1024 + d];
    float x = feat[(size_t)(b * NN + i) * DD + d];
    float P = gru_out(pir, piz, pin, gh[d], gh[512 + d], gh[1024 + d], x);
    float Hv = C + P;
    H[(size_t)(b * NN + i) * DD + d] = Hv;
    sred[d] = Hv * lin_w[512 + d];
    __syncthreads();
    for (int st = 256; st > 0; st >>= 1) {
        if (d < st) sred[d] += sred[d + st];
        __syncthreads();
    }
    if (d == 0) g_hk[b * NN + i] = sred[0];
}

// ---------------- launch ----------------------------------------------------
extern "C" void kernel_launch(void* const* d_in, const int* in_sizes, int n_in,
                              void* d_out, int out_size)
{
    const float* feat  = (const float*)d_in[0];
    const float* Wi_c  = (const float*)d_in[1];
    const float* Wh_c  = (const float*)d_in[2];
    const float* bi_c  = (const float*)d_in[3];
    const float* bh_c  = (const float*)d_in[4];
    const float* Wi_p  = (const float*)d_in[5];
    const float* Wh_p  = (const float*)d_in[6];
    const float* bi_p  = (const float*)d_in[7];
    const float* bh_p  = (const float*)d_in[8];
    const float* lin_w = (const float*)d_in[9];
    const float* lin_b = (const float*)d_in[10];
    const float* Wr0   = (const float*)d_in[11];
    const float* Wr1   = (const float*)d_in[12];
    const int*   adj   = (const int*)d_in[13];
    const int*   smask = (const int*)d_in[14];
    const int*   omask = (const int*)d_in[15];
    float* H = (float*)d_out;

    // Precompute x-side GRU gates for all (b, n):
    // g_gi = features @ Wi_c^T + bi_c ; g_gh = features @ Wh_p^T + bh_p
    dim3 gpre(D3 / 128, (BB * NN) / 128);
    gemm_nt_bias<<<gpre, 256>>>(feat, Wi_c, bi_c, 0, DD, DD, D3, DD);
    gemm_nt_bias<<<gpre, 256>>>(feat, Wh_p, bh_p, 1, DD, DD, D3, DD);

    // qdot + bias for all (b, n)
    qb_kernel<<<BB * NN, 128>>>(feat, lin_w, lin_b);

    // Step 0
    init_kernel<<<BB, 512>>>(feat, bh_c, bi_p, lin_w, H);

    // Steps 1..N-1
    for (int i = 1; i < NN; i++) {
        attn_kernel<<<BB, 256>>>(i, adj, smask, omask, H);
        step_gemm_M<<<dim3(8, 4), 256>>>(Wr0, Wr1);
        step_gemm_G<<<dim3(48, 2), 256>>>(Wh_c, Wi_p);
        gru_kernel<<<BB, 512>>>(i, feat, bh_c, bi_p, lin_w, H);
    }
}

// round 15
// speedup vs baseline: 1.9439x; 1.9439x over previous
#include <cuda_runtime.h>
#include <math.h>

#define BB 64
#define NN 128
#define DD 512
#define D3 1536
#define NBLK 128

// ---------------- scratch (device globals; no allocation) ----------------
__device__ float g_gi[BB * NN * D3];      // x @ Wi_c^T + bi_c
__device__ float g_gh[BB * NN * D3];      // x @ Wh_p^T + bh_p
__device__ float g_qb[BB * NN];           // x . wq + lin_b
__device__ float g_hk[BB * NN];           // H[b,n] . wk (incremental)
__device__ float g_u[BB * 2 * DD];        // [u0 | u1] weighted sums (64 x 1024)
__device__ float g_Mpart[8 * BB * DD];    // split-K partials of M
__device__ float g_M[BB * DD];            // reduced M (64 x 512)
__device__ float g_G[BB * 3072];          // gates = M @ [Wh_c;Wi_p]^T

// ---------------- software grid barrier (Round-10 proven) ----------------
__device__ unsigned g_cnt = 0;
__device__ volatile unsigned g_gen = 0;

__device__ __forceinline__ void grid_sync() {
    __syncthreads();
    if (threadIdx.x == 0) {
        __threadfence();
        unsigned gen = g_gen;
        if (atomicAdd(&g_cnt, 1u) == NBLK - 1) {
            g_cnt = 0;
            __threadfence();
            g_gen = gen + 1;
        } else {
            while (g_gen == gen) { __nanosleep(64); }
        }
    }
    __syncthreads();
}

__device__ __forceinline__ float gru_out(float ir, float iz, float inn,
                                         float hr, float hz, float hn, float h) {
    float r = 1.f / (1.f + expf(-(ir + hr)));
    float z = 1.f / (1.f + expf(-(iz + hz)));
    float n = tanhf(inn + r * hn);
    return (1.f - z) * n + z * h;
}

// ---------------- precompute GEMM: C[m,n] = sum_k A[m,k]*W[n,k] + bias[n] ----
__global__ __launch_bounds__(256) void gemm_nt_bias(
    const float* __restrict__ A, const float* __restrict__ W,
    const float* __restrict__ bias, int dst,
    int lda, int ldw, int ldc, int K)
{
    __shared__ __align__(16) float As[8][128];
    __shared__ __align__(16) float Ws[8][128];
    float* C = dst ? g_gh : g_gi;
    int t = threadIdx.x;
    int m0 = blockIdx.y * 128;
    int n0 = blockIdx.x * 128;
    int ar = t >> 1, ak = (t & 1) * 4;
    int ty = t >> 4, tx = t & 15;
    float acc[8][8];
#pragma unroll
    for (int i = 0; i < 8; i++)
#pragma unroll
        for (int j = 0; j < 8; j++) acc[i][j] = 0.f;

    for (int k0 = 0; k0 < K; k0 += 8) {
        float4 av = *(const float4*)(A + (size_t)(m0 + ar) * lda + k0 + ak);
        float4 wv = *(const float4*)(W + (size_t)(n0 + ar) * ldw + k0 + ak);
        As[ak + 0][ar] = av.x; As[ak + 1][ar] = av.y;
        As[ak + 2][ar] = av.z; As[ak + 3][ar] = av.w;
        Ws[ak + 0][ar] = wv.x; Ws[ak + 1][ar] = wv.y;
        Ws[ak + 2][ar] = wv.z; Ws[ak + 3][ar] = wv.w;
        __syncthreads();
#pragma unroll
        for (int k = 0; k < 8; k++) {
            float a[8], w[8];
            *(float4*)&a[0] = *(const float4*)&As[k][ty * 8];
            *(float4*)&a[4] = *(const float4*)&As[k][ty * 8 + 4];
            *(float4*)&w[0] = *(const float4*)&Ws[k][tx * 8];
            *(float4*)&w[4] = *(const float4*)&Ws[k][tx * 8 + 4];
#pragma unroll
            for (int i = 0; i < 8; i++)
#pragma unroll
                for (int j = 0; j < 8; j++) acc[i][j] += a[i] * w[j];
        }
        __syncthreads();
    }
#pragma unroll
    for (int i = 0; i < 8; i++) {
        int m = m0 + ty * 8 + i;
#pragma unroll
        for (int j = 0; j < 8; j++) {
            int n = n0 + tx * 8 + j;
            C[(size_t)m * ldc + n] = acc[i][j] + bias[n];
        }
    }
}

// ---------------- qb: g_qb[row] = features[row,:] . wq + lin_b -------------
__global__ __launch_bounds__(128) void qb_kernel(
    const float* __restrict__ feat, const float* __restrict__ lin_w,
    const float* __restrict__ lin_b)
{
    __shared__ float sred[128];
    int row = blockIdx.x;
    int t = threadIdx.x;
    const float* x = feat + (size_t)row * DD;
    float s = x[t] * lin_w[t] + x[t + 128] * lin_w[t + 128]
            + x[t + 256] * lin_w[t + 256] + x[t + 384] * lin_w[t + 384];
    sred[t] = s;
    __syncthreads();
    for (int st = 64; st > 0; st >>= 1) {
        if (t < st) sred[t] += sred[t + st];
        __syncthreads();
    }
    if (t == 0) g_qb[row] = sred[0] + lin_b[0];
}

// ---------------- fused attention for step j (block-local to batch b) -------
// Computes softmax weights over H[b, n<j] and writes u0/u1 to g_u.
__device__ __forceinline__ void attn_u(
    int b, int j, int t,
    const int* __restrict__ adj, const int* __restrict__ smask,
    const int* __restrict__ omask, const float* __restrict__ H,
    float* sa, float* sr, float* sws, float* swo)
{
    float a = -1e30f;
    int valid = 0;
    if (t < NN) {
        valid = (t < j) && adj[(size_t)(b * NN + j) * NN + t];
        if (valid) a = g_qb[b * NN + j] + __ldcg(&g_hk[b * NN + t]);
        sa[t] = a;
        sr[t] = a;
    }
    __syncthreads();
    for (int st = 64; st > 0; st >>= 1) {
        if (t < st) sr[t] = fmaxf(sr[t], sr[t + st]);
        __syncthreads();
    }
    float mx = sr[0];
    __syncthreads();
    float e = 0.f;
    if (t < NN) {
        e = valid ? expf(sa[t] - mx) : 0.f;
        sr[t] = e;
    }
    __syncthreads();
    for (int st = 64; st > 0; st >>= 1) {
        if (t < st) sr[t] += sr[t + st];
        __syncthreads();
    }
    float inv = 1.f / sr[0];
    if (t < NN) {
        float w = e * inv;
        int sm = 0, om = 0;
        if (valid) {
            sm = smask[(size_t)(b * NN + j) * NN + t];
            om = omask[(size_t)(b * NN + j) * NN + t];
        }
        sws[t] = w * (float)sm;
        swo[t] = w * (float)om;
    }
    __syncthreads();

    // one H load feeds BOTH weighted sums (d = t, 0..511)
    float u0 = 0.f, u1 = 0.f;
    const float* Hb = H + (size_t)b * NN * DD + t;
    for (int n = 0; n < j; n++) {
        float ws = sws[n], wo = swo[n];
        if (ws == 0.f && wo == 0.f) continue;   // uniform branch (smem)
        float h = __ldcg(Hb + (size_t)n * DD);
        u0 += ws * h;
        u1 += wo * h;
    }
    __stcg(&g_u[b * 1024 + t], u0);
    __stcg(&g_u[b * 1024 + 512 + t], u1);
}

// ---------------- persistent recurrence kernel ------------------------------
__global__ __launch_bounds__(512, 1) void grn_loop(
    const float* __restrict__ feat,
    const float* __restrict__ bh_c, const float* __restrict__ bi_p,
    const float* __restrict__ lin_w,
    const int* __restrict__ adj, const int* __restrict__ smask,
    const int* __restrict__ omask,
    const float* __restrict__ Wr0, const float* __restrict__ Wr1,
    const float* __restrict__ Whc, const float* __restrict__ Wip,
    float* __restrict__ H)
{
    __shared__ float sA[32 * 65];
    __shared__ float sW[32 * 33];
    __shared__ float sa[128], sr[128], sws[128], swo[128];
    __shared__ float sred[512];

    int blk = blockIdx.x;
    int t = threadIdx.x;

    // ======== init: H[:,0], hk[:,0], then fused A for step 1 (blocks < 64) ==
    if (blk < BB) {
        int b = blk, d = t;
        const float* gi = g_gi + (size_t)(b * NN) * D3;
        const float* gh = g_gh + (size_t)(b * NN) * D3;
        float Cv = gru_out(gi[d], gi[512 + d], gi[1024 + d],
                           bh_c[d], bh_c[512 + d], bh_c[1024 + d], 0.f);
        float x0 = feat[(size_t)(b * NN) * DD + d];
        float Pv = gru_out(bi_p[d], bi_p[512 + d], bi_p[1024 + d],
                           gh[d], gh[512 + d], gh[1024 + d], x0);
        float Hv = Cv + Pv;
        __stcg(&H[(size_t)(b * NN) * DD + d], Hv);
        sred[d] = Hv * lin_w[512 + d];
        __syncthreads();
        for (int st = 256; st > 0; st >>= 1) {
            if (d < st) sred[d] += sred[d + st];
            __syncthreads();
        }
        if (d == 0) __stcg(&g_hk[b * NN], sred[0]);
        __syncthreads();
        attn_u(b, 1, t, adj, smask, omask, H, sa, sr, sws, swo);
    }
    grid_sync();

    for (int i = 1; i < NN; i++) {
        // ======== B1: Mpart = u @ [Wr0|Wr1]^T (split-K x8, 128 blocks) ======
        {
            int kseg = blk >> 4, cs = blk & 15;
            int c0 = cs * 32;
            const float* Wm = (kseg < 4) ? Wr0 : Wr1;
            int kw0 = kseg * 128 - (kseg < 4 ? 0 : 512);
            int lr = t >> 3, kq = (t & 7) * 4;
            int rg = t >> 3, cg = t & 7;
            float acc[4][4];
#pragma unroll
            for (int ii = 0; ii < 4; ii++)
#pragma unroll
                for (int jj = 0; jj < 4; jj++) acc[ii][jj] = 0.f;

            float4 va = __ldcg((const float4*)(g_u + lr * 1024 + kseg * 128 + kq));
            float4 vw;
            if (t < 256)
                vw = *(const float4*)(Wm + (size_t)(c0 + lr) * 512 + kw0 + kq);
            sA[(kq + 0) * 65 + lr] = va.x; sA[(kq + 1) * 65 + lr] = va.y;
            sA[(kq + 2) * 65 + lr] = va.z; sA[(kq + 3) * 65 + lr] = va.w;
            if (t < 256) {
                sW[(kq + 0) * 33 + lr] = vw.x; sW[(kq + 1) * 33 + lr] = vw.y;
                sW[(kq + 2) * 33 + lr] = vw.z; sW[(kq + 3) * 33 + lr] = vw.w;
            }
            __syncthreads();

            for (int kk = 0; kk < 128; kk += 32) {
                int more = (kk + 32 < 128);
                if (more) {
                    va = __ldcg((const float4*)(g_u + lr * 1024 + kseg * 128 + kk + 32 + kq));
                    if (t < 256)
                        vw = *(const float4*)(Wm + (size_t)(c0 + lr) * 512 + kw0 + kk + 32 + kq);
                }
                if (t < 128) {
#pragma unroll
                    for (int k = 0; k < 32; k++) {
                        float a0 = sA[k * 65 + rg * 4 + 0];
                        float a1 = sA[k * 65 + rg * 4 + 1];
                        float a2 = sA[k * 65 + rg * 4 + 2];
                        float a3 = sA[k * 65 + rg * 4 + 3];
                        float w0 = sW[k * 33 + cg * 4 + 0];
                        float w1 = sW[k * 33 + cg * 4 + 1];
                        float w2 = sW[k * 33 + cg * 4 + 2];
                        float w3 = sW[k * 33 + cg * 4 + 3];
                        acc[0][0] += a0 * w0; acc[0][1] += a0 * w1;
                        acc[0][2] += a0 * w2; acc[0][3] += a0 * w3;
                        acc[1][0] += a1 * w0; acc[1][1] += a1 * w1;
                        acc[1][2] += a1 * w2; acc[1][3] += a1 * w3;
                        acc[2][0] += a2 * w0; acc[2][1] += a2 * w1;
                        acc[2][2] += a2 * w2; acc[2][3] += a2 * w3;
                        acc[3][0] += a3 * w0; acc[3][1] += a3 * w1;
                        acc[3][2] += a3 * w2; acc[3][3] += a3 * w3;
                    }
                }
                __syncthreads();
                if (more) {
                    sA[(kq + 0) * 65 + lr] = va.x; sA[(kq + 1) * 65 + lr] = va.y;
                    sA[(kq + 2) * 65 + lr] = va.z; sA[(kq + 3) * 65 + lr] = va.w;
                    if (t < 256) {
                        sW[(kq + 0) * 33 + lr] = vw.x; sW[(kq + 1) * 33 + lr] = vw.y;
                        sW[(kq + 2) * 33 + lr] = vw.z; sW[(kq + 3) * 33 + lr] = vw.w;
                    }
                    __syncthreads();
                }
            }
            if (t < 128) {
#pragma unroll
                for (int ii = 0; ii < 4; ii++)
#pragma unroll
                    for (int jj = 0; jj < 4; jj++)
                        __stcg(&g_Mpart[(size_t)(kseg * 64 + rg * 4 + ii) * 512
                                        + c0 + cg * 4 + jj], acc[ii][jj]);
            }
        }
        grid_sync();

        // ======== R: reduce Mpart -> M (all 128 blocks, 256 elems each) =====
        if (t < 256) {
            int idx = blk * 256 + t;
            float s = 0.f;
#pragma unroll
            for (int ks = 0; ks < 8; ks++)
                s += __ldcg(&g_Mpart[(size_t)ks * BB * DD + idx]);
            __stcg(&g_M[idx], s);
        }
        grid_sync();

        // ======== B2: G = M @ [Wh_c;Wi_p]^T (128 blocks, 64x24 tiles) =======
        {
            int c0 = blk * 24;
            const float* Wg = (c0 < 1536) ? (Whc + (size_t)c0 * 512)
                                          : (Wip + (size_t)(c0 - 1536) * 512);
            int lr = t >> 3, kq = (t & 7) * 4;
            int rg = t >> 3, cg = t & 7;
            float acc[4][3];
#pragma unroll
            for (int ii = 0; ii < 4; ii++)
#pragma unroll
                for (int jj = 0; jj < 3; jj++) acc[ii][jj] = 0.f;

            float4 va = __ldcg((const float4*)(g_M + lr * 512 + kq));
            float4 vw;
            if (t < 192)
                vw = *(const float4*)(Wg + (size_t)lr * 512 + kq);
            sA[(kq + 0) * 65 + lr] = va.x; sA[(kq + 1) * 65 + lr] = va.y;
            sA[(kq + 2) * 65 + lr] = va.z; sA[(kq + 3) * 65 + lr] = va.w;
            if (t < 192) {
                sW[(kq + 0) * 25 + lr] = vw.x; sW[(kq + 1) * 25 + lr] = vw.y;
                sW[(kq + 2) * 25 + lr] = vw.z; sW[(kq + 3) * 25 + lr] = vw.w;
            }
            __syncthreads();

            for (int kk = 0; kk < 512; kk += 32) {
                int more = (kk + 32 < 512);
                if (more) {
                    va = __ldcg((const float4*)(g_M + lr * 512 + kk + 32 + kq));
                    if (t < 192)
                        vw = *(const float4*)(Wg + (size_t)lr * 512 + kk + 32 + kq);
                }
                if (t < 128) {
#pragma unroll
                    for (int k = 0; k < 32; k++) {
                        float a0 = sA[k * 65 + rg * 4 + 0];
                        float a1 = sA[k * 65 + rg * 4 + 1];
                        float a2 = sA[k * 65 + rg * 4 + 2];
                        float a3 = sA[k * 65 + rg * 4 + 3];
                        float w0 = sW[k * 25 + cg * 3 + 0];
                        float w1 = sW[k * 25 + cg * 3 + 1];
                        float w2 = sW[k * 25 + cg * 3 + 2];
                        acc[0][0] += a0 * w0; acc[0][1] += a0 * w1; acc[0][2] += a0 * w2;
                        acc[1][0] += a1 * w0; acc[1][1] += a1 * w1; acc[1][2] += a1 * w2;
                        acc[2][0] += a2 * w0; acc[2][1] += a2 * w1; acc[2][2] += a2 * w2;
                        acc[3][0] += a3 * w0; acc[3][1] += a3 * w1; acc[3][2] += a3 * w2;
                    }
                }
                __syncthreads();
                if (more) {
                    sA[(kq + 0) * 65 + lr] = va.x; sA[(kq + 1) * 65 + lr] = va.y;
                    sA[(kq + 2) * 65 + lr] = va.z; sA[(kq + 3) * 65 + lr] = va.w;
                    if (t < 192) {
                        sW[(kq + 0) * 25 + lr] = vw.x; sW[(kq + 1) * 25 + lr] = vw.y;
                        sW[(kq + 2) * 25 + lr] = vw.z; sW[(kq + 3) * 25 + lr] = vw.w;
                    }
                    __syncthreads();
                }
            }
            if (t < 128) {
#pragma unroll
                for (int ii = 0; ii < 4; ii++)
#pragma unroll
                    for (int jj = 0; jj < 3; jj++)
                        __stcg(&g_G[(size_t)(rg * 4 + ii) * 3072 + c0 + cg * 3 + jj],
                               acc[ii][jj]);
            }
        }
        grid_sync();

        // ======== CA: GRU -> H[:,i], hk[:,i]; then fused A for step i+1 =====
        if (blk < BB) {
            int b = blk, d = t;
            float Mv = __ldcg(&g_M[b * 512 + d]);
            const float* gi = g_gi + (size_t)(b * NN + i) * D3;
            const float* gh = g_gh + (size_t)(b * NN + i) * D3;
            const float* gb = g_G + (size_t)b * 3072;
            float hr = __ldcg(&gb[d])        + bh_c[d];
            float hz = __ldcg(&gb[512 + d])  + bh_c[512 + d];
            float hn = __ldcg(&gb[1024 + d]) + bh_c[1024 + d];
            float Cv = gru_out(gi[d], gi[512 + d], gi[1024 + d], hr, hz, hn, Mv);
            float pir = __ldcg(&gb[1536 + d]) + bi_p[d];
            float piz = __ldcg(&gb[2048 + d]) + bi_p[512 + d];
            float pin = __ldcg(&gb[2560 + d]) + bi_p[1024 + d];
            float x = feat[(size_t)(b * NN + i) * DD + d];
            float Pv = gru_out(pir, piz, pin, gh[d], gh[512 + d], gh[1024 + d], x);
            float Hv = Cv + Pv;
            __stcg(&H[(size_t)(b * NN + i) * DD + d], Hv);
            sred[d] = Hv * lin_w[512 + d];
            __syncthreads();
            for (int st = 256; st > 0; st >>= 1) {
                if (d < st) sred[d] += sred[d + st];
                __syncthreads();
            }
            if (d == 0) __stcg(&g_hk[b * NN + i], sred[0]);
            __syncthreads();
            if (i + 1 < NN)
                attn_u(b, i + 1, t, adj, smask, omask, H, sa, sr, sws, swo);
        }
        if (i + 1 < NN) grid_sync();
    }
}

// ---------------- launch ----------------------------------------------------
extern "C" void kernel_launch(void* const* d_in, const int* in_sizes, int n_in,
                              void* d_out, int out_size)
{
    const float* feat  = (const float*)d_in[0];
    const float* Wi_c  = (const float*)d_in[1];
    const float* Wh_c  = (const float*)d_in[2];
    const float* bi_c  = (const float*)d_in[3];
    const float* bh_c  = (const float*)d_in[4];
    const float* Wi_p  = (const float*)d_in[5];
    const float* Wh_p  = (const float*)d_in[6];
    const float* bi_p  = (const float*)d_in[7];
    const float* bh_p  = (const float*)d_in[8];
    const float* lin_w = (const float*)d_in[9];
    const float* lin_b = (const float*)d_in[10];
    const float* Wr0   = (const float*)d_in[11];
    const float* Wr1   = (const float*)d_in[12];
    const int*   adj   = (const int*)d_in[13];
    const int*   smask = (const int*)d_in[14];
    const int*   omask = (const int*)d_in[15];
    float* H = (float*)d_out;

    // Precompute x-side GRU gates for all (b, n)
    dim3 gpre(D3 / 128, (BB * NN) / 128);
    gemm_nt_bias<<<gpre, 256>>>(feat, Wi_c, bi_c, 0, DD, DD, D3, DD);
    gemm_nt_bias<<<gpre, 256>>>(feat, Wh_p, bh_p, 1, DD, DD, D3, DD);
    qb_kernel<<<BB * NN, 128>>>(feat, lin_w, lin_b);

    // Entire recurrence in one persistent kernel with grid-wide sync
    grn_loop<<<NBLK, 512>>>(feat, bh_c, bi_p, lin_w, adj, smask, omask,
                            Wr0, Wr1, Wh_c, Wi_p, H);
}